// round 12
// baseline (speedup 1.0000x reference)
#include <cuda_runtime.h>

#define BATCH 8
#define NCH   6
#define HH    1024
#define WW    1024
#define TX    64
#define TY    64
#define HY    68      // halo rows: [by-2, by+66)
#define NPIX  (8.0f * 1024.0f * 1024.0f)
#define PIX_PER_B (HH * WW)          // 1<<20
#define CH_STRIDE4 (PIX_PER_B / 4)   // 262144

__device__ unsigned g_code4[(BATCH * PIX_PER_B) / 4];   // 8 MiB: 4 packed bytes/word

// ---- Kernel A: streaming argmax + pack (4 pixels/thread) ----
__global__ __launch_bounds__(256) void dcl_classify(
    const float* __restrict__ pred, const void* __restrict__ tgt,
    float* __restrict__ out)
{
    // Targets in [0,5]; little-endian int64 => odd 32-bit words of the first
    // 64 elements all zero. P(false positive for int32) = (1/6)^32 ~ 0.
    const int lane = threadIdx.x & 31;
    const int probe = ((const int*)tgt)[2 * lane + 1];
    const int is64 = (__ballot_sync(0xffffffffu, probe != 0) == 0u);

    const unsigned t = blockIdx.x * 256u + threadIdx.x;     // pixel4 index
    if (t == 0) *out = 0.0f;
    const unsigned b   = t >> 18;
    const unsigned off = t & 0x3FFFFu;

    const float4* pp = (const float4*)pred + (size_t)b * NCH * CH_STRIDE4 + off;
    float4 v[NCH];
    #pragma unroll
    for (int ch = 0; ch < NCH; ++ch) v[ch] = pp[(size_t)ch * CH_STRIDE4];

    int t0, t1, t2, t3;
    if (is64) {
        const int4* tp = (const int4*)tgt + (size_t)t * 2;
        const int4 q0 = tp[0], q1 = tp[1];
        t0 = q0.x; t1 = q0.z; t2 = q1.x; t3 = q1.z;
    } else {
        const int4 q = ((const int4*)tgt)[t];
        t0 = q.x; t1 = q.y; t2 = q.z; t3 = q.w;
    }

    int i0 = 0, i1 = 0, i2 = 0, i3 = 0;
    float m0 = v[0].x, m1 = v[0].y, m2 = v[0].z, m3 = v[0].w;
    #pragma unroll
    for (int ch = 1; ch < NCH; ++ch) {
        if (v[ch].x > m0) { m0 = v[ch].x; i0 = ch; }
        if (v[ch].y > m1) { m1 = v[ch].y; i1 = ch; }
        if (v[ch].z > m2) { m2 = v[ch].z; i2 = ch; }
        if (v[ch].w > m3) { m3 = v[ch].w; i3 = ch; }
    }

    g_code4[t] = (unsigned)(i0 | (t0 << 4))
               | ((unsigned)(i1 | (t1 << 4)) << 8)
               | ((unsigned)(i2 | (t2 << 4)) << 16)
               | ((unsigned)(i3 | (t3 << 4)) << 24);
}

// ---- Kernel B: lean stencil + MSE reduce ----
// hbuf[r][c]: 4 x 8-bit fields = h5sum(cv) | h5sum(cv^2)<<8
//                              | h5sum(tv)<<16 | h5sum(tv^2)<<24
// (<=25 / <=125 / <=25 / <=125 — no field carry.)
__global__ __launch_bounds__(512) void dcl_stencil(float* __restrict__ out)
{
    __shared__ unsigned hbuf[HY][TX];   // 17.4 KB

    const int tid = threadIdx.x;
    const int bx  = blockIdx.x * TX;
    const int by  = blockIdx.y * TY;
    const unsigned base_w = ((unsigned)blockIdx.z << 18);

    // ---- Phase A: horizontal 5-sums straight from global code words ----
    for (int i = tid; i < HY * (TX / 4); i += 512) {
        const int rr = i >> 4;              // halo row 0..67
        const int cw = i & 15;              // word-col within tile
        const int gy = by + rr - 2;
        unsigned wm = 0, w0 = 0, wp = 0;
        if ((unsigned)gy < (unsigned)HH) {
            const unsigned rowbase = base_w + ((unsigned)gy << 8);
            const int wc = (bx >> 2) + cw;  // 0..255
            if (wc > 0)   wm = g_code4[rowbase + wc - 1];
            w0 = g_code4[rowbase + wc];
            if (wc < 255) wp = g_code4[rowbase + wc + 1];
        }
        // code bytes covering cols gx-2..gx+5
        unsigned e[8];
        e[0] = (wm >> 16) & 255u;  e[1] = wm >> 24;
        e[2] =  w0        & 255u;  e[3] = (w0 >> 8) & 255u;
        e[4] = (w0 >> 16) & 255u;  e[5] =  w0 >> 24;
        e[6] =  wp        & 255u;  e[7] = (wp >> 8) & 255u;
        unsigned m[8];
        #pragma unroll
        for (int j = 0; j < 8; ++j) {
            const unsigned cv = e[j] & 15u, tv = e[j] >> 4;
            m[j] = cv * ((cv << 8) + 1u) + ((tv * ((tv << 8) + 1u)) << 16);
        }
        unsigned s = m[0] + m[1] + m[2] + m[3] + m[4];
        uint4 o;
        o.x = s; s += m[5] - m[0];
        o.y = s; s += m[6] - m[1];
        o.z = s; s += m[7] - m[2];
        o.w = s;
        *(uint4*)&hbuf[rr][cw * 4] = o;
    }
    __syncthreads();

    // ---- Phase B: vertical sliding 5-window, 1 col x 8 rows per thread ----
    // Split each h-word into lo = s1c|s1t<<16 and hi = s2c|s2t<<16 (16-bit
    // fields; vertical 5-sums reach 125 / 625 — no carry).
    const int c  = tid & 63;
    const int r0 = (tid >> 6) * 8;

    unsigned lo[12], hi[12];
    #pragma unroll
    for (int d = 0; d < 12; ++d) {
        const unsigned w = hbuf[r0 + d][c];
        lo[d] = w & 0x00FF00FFu;
        hi[d] = (w >> 8) & 0x00FF00FFu;
    }
    unsigned sa = lo[0] + lo[1] + lo[2] + lo[3] + lo[4];
    unsigned sb = hi[0] + hi[1] + hi[2] + hi[3] + hi[4];

    int   acc_i = 0;
    float acc_s = 0.0f;
    #pragma unroll
    for (int rr = 0; rr < 8; ++rr) {
        // q = 25*sb evaluates both 25*s2 fields at once (25*625=15625 < 2^16).
        const unsigned q = sb * 25u;
        const int s1c = (int)(sa & 0xFFFFu), s1t = (int)(sa >> 16);
        const int np = (int)(q & 0xFFFFu) - s1c * s1c;   // exact, [0,15625]
        const int nt = (int)(q >> 16)     - s1t * s1t;
        acc_i += np + nt;
        // (sqrt(np/600)-sqrt(nt/600))^2 = (np + nt - 2*sqrt(np*nt))/600
        const float p = (float)(np * nt);
        float s;
        asm("sqrt.approx.f32 %0, %1;" : "=f"(s) : "f"(p));
        acc_s += s;
        if (rr < 7) { sa += lo[rr + 5] - lo[rr]; sb += hi[rr + 5] - hi[rr]; }
    }

    float acc = fmaf(-2.0f, acc_s, (float)acc_i) * (1.0f / (600.0f * NPIX));

    // ---- Reduce: warp shuffle -> smem -> one atomic per block ----
    #pragma unroll
    for (int o = 16; o > 0; o >>= 1)
        acc += __shfl_down_sync(0xffffffffu, acc, o);

    __shared__ float warpsum[16];
    if ((tid & 31) == 0) warpsum[tid >> 5] = acc;
    __syncthreads();
    if (tid < 16) {
        float v = warpsum[tid];
        #pragma unroll
        for (int o = 8; o > 0; o >>= 1)
            v += __shfl_down_sync(0xffffu, v, o);
        if (tid == 0) atomicAdd(out, v);
    }
}

extern "C" void kernel_launch(void* const* d_in, const int* in_sizes, int n_in,
                              void* d_out, int out_size) {
    const float* pred = (const float*)d_in[0];
    const void*  tgt  = d_in[1];
    float* out = (float*)d_out;

    const int n_p4_blocks = (BATCH * PIX_PER_B / 4) / 256;   // 8192
    dcl_classify<<<n_p4_blocks, 256>>>(pred, tgt, out);

    dim3 grid(WW / TX, HH / TY, BATCH);
    dcl_stencil<<<grid, 512>>>(out);
}